// round 7
// baseline (speedup 1.0000x reference)
#include <cuda_runtime.h>
#include <cuda_fp16.h>
#include <cstddef>
#include <cstdint>

// ---------------------------------------------------------------------------
// GeoDynamicLayer: out = x @ W^T, W = RK4(dU/dt = U A + G).
// Factored RK4: row space of all stages spanned by V2=[La|Ra|Rb] (512x24).
// RK4 is linear in (p, f0):  p' = p*Phi + f0*Psi  with the RK4 polynomials
//   Phi = I + hS + h^2S^2/2 + h^3S^3/6 + h^4S^4/24
//   Psi = h(I + hS/2 + h^2S^2/6 + h^3S^3/24)
// so after 8 steps from p0=0:  P = F0 * PsiTot, PsiTot = Psi*(I+Phi+...+Phi^7)
// => W = U0 + F0 * Qt^T where Qt[i][k] = sum_c PsiTot[k][c] V2[i][c].
// Final GEMM: single-pass fp16 HMMA (x, W in fp16, fp32 accumulate).
// ---------------------------------------------------------------------------

__device__ float g_partial[256 * 512];
__device__ float g_ab[16];
__device__ float g_S[24 * 16];
__device__ float g_F0[1024 * 24];
__device__ float g_Qt[512 * 24];
__device__ __half g_x16[32768 * 512];
__device__ __half g_W16[1024 * 512];

// ---------------- Stage 1: convert x -> fp16 + column partial sums ----------
__global__ void convert_reduce_k(const float* __restrict__ x) {
    int t = threadIdx.x;                 // 0..511 = column
    int rowStart = blockIdx.x * 128;
    const float* p = x + (size_t)rowStart * 512 + t;
    float s = 0.f;
    #pragma unroll 4
    for (int r = 0; r < 128; ++r) {
        float v = p[(size_t)r * 512];
        s += v;
        g_x16[(size_t)(rowStart + r) * 512 + t] = __float2half_rn(v);
    }
    g_partial[blockIdx.x * 512 + t] = s;
}

// ---------------- Stage 2: xbar, abar, bbar ---------------------------------
__global__ void finalize_ab_k(const float* __restrict__ Wa,
                              const float* __restrict__ Wb) {
    __shared__ float sx[512];
    int t = threadIdx.x;
    float s = 0.f;
    #pragma unroll 8
    for (int p = 0; p < 256; ++p) s += g_partial[p * 512 + t];
    s *= (1.0f / 32768.0f);
    sx[t] = s;
    __syncthreads();
    int w = t >> 5, lane = t & 31;
    const float* Wm = (w < 8) ? Wa : Wb;
    int r = w & 7;
    float acc = 0.f;
    #pragma unroll
    for (int q = 0; q < 16; ++q) {
        int i = lane + q * 32;
        acc += sx[i] * Wm[i * 8 + r];
    }
    #pragma unroll
    for (int off = 16; off; off >>= 1)
        acc += __shfl_xor_sync(0xffffffffu, acc, off);
    if (lane == 0) g_ab[w] = acc;
}

// ---------------- Stage 3: S (24x16) ----------------------------------------
__global__ void compute_S_k(const float* __restrict__ La,
                            const float* __restrict__ Ra,
                            const float* __restrict__ Rb) {
    int gw = (blockIdx.x * blockDim.x + threadIdx.x) >> 5;
    int lane = threadIdx.x & 31;
    if (gw >= 384) return;
    int k = gw >> 4, c = gw & 15;
    const float* Vk = (k < 8) ? La : ((k < 16) ? Ra : Rb);
    int kk = k & 7;
    const float* M = (c < 8) ? Ra : La;
    int r = c & 7;
    float acc = 0.f;
    #pragma unroll
    for (int q = 0; q < 16; ++q) {
        int i = lane + q * 32;
        acc += Vk[i * 8 + kk] * M[i * 8 + r];
    }
    #pragma unroll
    for (int off = 16; off; off >>= 1)
        acc += __shfl_xor_sync(0xffffffffu, acc, off);
    if (lane == 0) {
        float d = g_ab[r];
        g_S[k * 16 + c] = (c < 8) ? (-acc * d) : (acc * d);
    }
}

// ---------------- Stage 4: F0 (1024x24), no warp reductions -----------------
// Warp handles 2 rows; lane = (rowhalf<<4)|o, o<8: dot(u, La[:,o]) -> F0 col
// 8+o scaled by +ab[o];  o in 8..15: dot(u, Ra[:,o-8]) -> F0 col o-8 scaled
// by -ab[o-8].  Lb forcing written by the o<8 lanes.
__global__ void compute_F0_k(const float* __restrict__ U0,
                             const float* __restrict__ La,
                             const float* __restrict__ Ra,
                             const float* __restrict__ Lb) {
    int gw = (blockIdx.x * blockDim.x + threadIdx.x) >> 5;   // 0..511
    int lane = threadIdx.x & 31;
    int row = gw * 2 + (lane >> 4);
    int o = lane & 15;
    const float* M = (o < 8) ? La : Ra;
    int r = o & 7;
    const float* u = U0 + (size_t)row * 512;
    float a0 = 0.f, a1 = 0.f, a2 = 0.f, a3 = 0.f;
    #pragma unroll 4
    for (int k = 0; k < 512; k += 4) {
        a0 += u[k + 0] * M[(k + 0) * 8 + r];
        a1 += u[k + 1] * M[(k + 1) * 8 + r];
        a2 += u[k + 2] * M[(k + 2) * 8 + r];
        a3 += u[k + 3] * M[(k + 3) * 8 + r];
    }
    float acc = (a0 + a1) + (a2 + a3);
    float da = g_ab[r];
    if (o < 8) {
        g_F0[row * 24 + 8 + r] = da * acc;
        float gb = 0.f;
        if (row >= 512) gb = g_ab[8 + r] * Lb[(row - 512) * 8 + r];
        g_F0[row * 24 + 16 + r] = gb;
    } else {
        g_F0[row * 24 + r] = -da * acc;
    }
}

// ---------------- Stage 5: PsiTot (24x24) + Qt (512x24), one block ----------
__device__ __forceinline__ void mm24(float* D, const float* A, const float* B,
                                     int t) {
    for (int e = t; e < 576; e += 256) {
        int i = e / 24, j = e % 24;
        float a = 0.f;
        #pragma unroll
        for (int m = 0; m < 24; ++m) a += A[i * 24 + m] * B[m * 24 + j];
        D[e] = a;
    }
}

__global__ void psi_k(const float* __restrict__ La,
                      const float* __restrict__ Ra,
                      const float* __restrict__ Rb) {
    __shared__ float S1[576], S2[576], S3[576], S4[576];
    __shared__ float Phi[576], Psi[576], Sum[576], Cur[576], Tmp[576], Pt[576];
    int t = threadIdx.x;                 // 256 threads
    for (int e = t; e < 576; e += 256) {
        int i = e / 24, j = e % 24;
        S1[e] = (j < 16) ? g_S[i * 16 + j] : 0.f;
    }
    __syncthreads();
    mm24(S2, S1, S1, t); __syncthreads();
    mm24(S3, S2, S1, t); __syncthreads();
    mm24(S4, S3, S1, t); __syncthreads();
    const float h = 0.125f;
    for (int e = t; e < 576; e += 256) {
        int i = e / 24, j = e % 24;
        float id = (i == j) ? 1.f : 0.f;
        float phi = id + h * S1[e] + (h * h * 0.5f) * S2[e]
                  + (h * h * h / 6.f) * S3[e] + (h * h * h * h / 24.f) * S4[e];
        Phi[e] = phi;
        Psi[e] = h * (id + (h * 0.5f) * S1[e] + (h * h / 6.f) * S2[e]
                      + (h * h * h / 24.f) * S3[e]);
        Sum[e] = id + phi;
        Cur[e] = phi;
    }
    __syncthreads();
    for (int s = 0; s < 6; ++s) {
        mm24(Tmp, Cur, Phi, t);
        __syncthreads();
        for (int e = t; e < 576; e += 256) {
            Cur[e] = Tmp[e];
            Sum[e] += Tmp[e];
        }
        __syncthreads();
    }
    mm24(Pt, Psi, Sum, t);               // PsiTot
    __syncthreads();
    // Qt[i][k] = sum_c PsiTot[k][c] * V2[i][c],  V2 = [La | Ra | Rb]
    #pragma unroll
    for (int half = 0; half < 2; ++half) {
        int i = t + half * 256;
        float v2[24];
        float4 q;
        q = *(const float4*)(La + i * 8);
        v2[0] = q.x; v2[1] = q.y; v2[2] = q.z; v2[3] = q.w;
        q = *(const float4*)(La + i * 8 + 4);
        v2[4] = q.x; v2[5] = q.y; v2[6] = q.z; v2[7] = q.w;
        q = *(const float4*)(Ra + i * 8);
        v2[8] = q.x; v2[9] = q.y; v2[10] = q.z; v2[11] = q.w;
        q = *(const float4*)(Ra + i * 8 + 4);
        v2[12] = q.x; v2[13] = q.y; v2[14] = q.z; v2[15] = q.w;
        q = *(const float4*)(Rb + i * 8);
        v2[16] = q.x; v2[17] = q.y; v2[18] = q.z; v2[19] = q.w;
        q = *(const float4*)(Rb + i * 8 + 4);
        v2[20] = q.x; v2[21] = q.y; v2[22] = q.z; v2[23] = q.w;
        #pragma unroll
        for (int k = 0; k < 24; ++k) {
            float a = 0.f;
            #pragma unroll
            for (int c = 0; c < 24; ++c) a += Pt[k * 24 + c] * v2[c];
            g_Qt[i * 24 + k] = a;
        }
    }
}

// ---------------- Stage 6: W = U0 + F0*Qt^T -> fp16 -------------------------
__global__ void expand_W_k(const float* __restrict__ U0) {
    __shared__ float sF0[4 * 24];
    int t = threadIdx.x;                 // 256 threads
    int o0 = blockIdx.x * 4;             // 256 blocks x 4 rows
    if (t < 96) sF0[t] = g_F0[o0 * 24 + t];
    __syncthreads();
    #pragma unroll
    for (int half = 0; half < 2; ++half) {
        int i = t + half * 256;          // column 0..511
        float qv[24];
        const float4* qp = (const float4*)(g_Qt + i * 24);
        #pragma unroll
        for (int v = 0; v < 6; ++v) {
            float4 q = qp[v];
            qv[v * 4 + 0] = q.x; qv[v * 4 + 1] = q.y;
            qv[v * 4 + 2] = q.z; qv[v * 4 + 3] = q.w;
        }
        #pragma unroll
        for (int r = 0; r < 4; ++r) {
            float accv = U0[(size_t)(o0 + r) * 512 + i];
            #pragma unroll
            for (int k = 0; k < 24; ++k) accv += sF0[r * 24 + k] * qv[k];
            g_W16[(size_t)(o0 + r) * 512 + i] = __float2half_rn(accv);
        }
    }
}

// ---------------- Stage 7: fp16 HMMA GEMM  out = x @ W^T --------------------
#define CP16(sa, ga) \
    asm volatile("cp.async.cg.shared.global [%0], [%1], 16;\n" :: "r"(sa), "l"(ga))

__device__ __forceinline__ void ldm_x4(uint32_t& r0, uint32_t& r1,
                                       uint32_t& r2, uint32_t& r3, uint32_t a) {
    asm volatile("ldmatrix.sync.aligned.m8n8.x4.shared.b16 {%0,%1,%2,%3}, [%4];"
                 : "=r"(r0), "=r"(r1), "=r"(r2), "=r"(r3) : "r"(a));
}

__device__ __forceinline__ void mma16816(float* c, const uint32_t* a,
                                         const uint32_t* b) {
    asm volatile(
        "mma.sync.aligned.m16n8k16.row.col.f32.f16.f16.f32 "
        "{%0,%1,%2,%3}, {%4,%5,%6,%7}, {%8,%9}, {%0,%1,%2,%3};"
        : "+f"(c[0]), "+f"(c[1]), "+f"(c[2]), "+f"(c[3])
        : "r"(a[0]), "r"(a[1]), "r"(a[2]), "r"(a[3]), "r"(b[0]), "r"(b[1]));
}

__global__ __launch_bounds__(256) void gemm_tc_k(float* __restrict__ out) {
    __shared__ __align__(16) __half smA[2][128 * 5 * 8];
    __shared__ __align__(16) __half smB[2][128 * 5 * 8];

    int tid = threadIdx.x;
    int lane = tid & 31;
    int w = tid >> 5;
    int wm = (w & 3) * 32;
    int wn = (w >> 2) * 64;
    int bm = blockIdx.y * 128;
    int bn = blockIdx.x * 128;

    uint32_t saA[2], saB[2];
    saA[0] = (uint32_t)__cvta_generic_to_shared(&smA[0][0]);
    saA[1] = (uint32_t)__cvta_generic_to_shared(&smA[1][0]);
    saB[0] = (uint32_t)__cvta_generic_to_shared(&smB[0][0]);
    saB[1] = (uint32_t)__cvta_generic_to_shared(&smB[1][0]);

    float c[2][8][4];
    #pragma unroll
    for (int mi = 0; mi < 2; ++mi)
        #pragma unroll
        for (int ni = 0; ni < 8; ++ni)
            #pragma unroll
            for (int q = 0; q < 4; ++q) c[mi][ni][q] = 0.f;

    int lr0 = tid >> 2;
    int lu = tid & 3;

    auto issue_chunk = [&](int i, int buf) {
        int ko = i << 5;
        #pragma unroll
        for (int j = 0; j < 2; ++j) {
            int r = lr0 + j * 64;
            const __half* ga = g_x16 + (size_t)(bm + r) * 512 + ko + lu * 8;
            CP16(saA[buf] + ((r * 5 + lu) << 4), ga);
            const __half* gb = g_W16 + (size_t)(bn + r) * 512 + ko + lu * 8;
            CP16(saB[buf] + ((r * 5 + lu) << 4), gb);
        }
        asm volatile("cp.async.commit_group;\n" ::);
    };

    issue_chunk(0, 0);

    int mg = lane >> 3, rr = lane & 7;

    for (int i = 0; i < 16; ++i) {
        int buf = i & 1;
        if (i + 1 < 16) {
            issue_chunk(i + 1, buf ^ 1);
            asm volatile("cp.async.wait_group 1;\n" ::);
        } else {
            asm volatile("cp.async.wait_group 0;\n" ::);
        }
        __syncthreads();

        #pragma unroll
        for (int ks = 0; ks < 2; ++ks) {
            uint32_t a[2][4];
            #pragma unroll
            for (int mi = 0; mi < 2; ++mi) {
                int row = wm + mi * 16 + (mg & 1) * 8 + rr;
                int ku = ks * 2 + (mg >> 1);
                ldm_x4(a[mi][0], a[mi][1], a[mi][2], a[mi][3],
                       saA[buf] + ((row * 5 + ku) << 4));
            }
            uint32_t b[8][2];
            #pragma unroll
            for (int j = 0; j < 4; ++j) {
                int row = wn + j * 16 + (mg >> 1) * 8 + rr;
                int ku = ks * 2 + (mg & 1);
                ldm_x4(b[2 * j][0], b[2 * j][1], b[2 * j + 1][0], b[2 * j + 1][1],
                       saB[buf] + ((row * 5 + ku) << 4));
            }
            #pragma unroll
            for (int mi = 0; mi < 2; ++mi)
                #pragma unroll
                for (int ni = 0; ni < 8; ++ni)
                    mma16816(c[mi][ni], a[mi], b[ni]);
        }
        __syncthreads();
    }

    int gid = lane >> 2, tig = lane & 3;
    #pragma unroll
    for (int mi = 0; mi < 2; ++mi) {
        #pragma unroll
        for (int ni = 0; ni < 8; ++ni) {
            int row0 = bm + wm + mi * 16 + gid;
            int col = bn + wn + ni * 8 + tig * 2;
            float2* p0 = (float2*)(out + (size_t)row0 * 1024 + col);
            *p0 = make_float2(c[mi][ni][0], c[mi][ni][1]);
            float2* p1 = (float2*)(out + (size_t)(row0 + 8) * 1024 + col);
            *p1 = make_float2(c[mi][ni][2], c[mi][ni][3]);
        }
    }
}

// ---------------------------------------------------------------------------
extern "C" void kernel_launch(void* const* d_in, const int* in_sizes, int n_in,
                              void* d_out, int out_size) {
    const float* x  = (const float*)d_in[0];
    const float* U0 = (const float*)d_in[1];
    const float* Wa = (const float*)d_in[2];
    const float* La = (const float*)d_in[3];
    const float* Ra = (const float*)d_in[4];
    const float* Wb = (const float*)d_in[5];
    const float* Lb = (const float*)d_in[6];
    const float* Rb = (const float*)d_in[7];
    float* out = (float*)d_out;
    (void)in_sizes; (void)n_in; (void)out_size;

    convert_reduce_k<<<256, 512>>>(x);
    finalize_ab_k<<<1, 512>>>(Wa, Wb);
    compute_S_k<<<48, 256>>>(La, Ra, Rb);
    compute_F0_k<<<64, 256>>>(U0, La, Ra, Lb);
    psi_k<<<1, 256>>>(La, Ra, Rb);
    expand_W_k<<<256, 256>>>(U0);
    gemm_tc_k<<<dim3(8, 256), 256>>>(out);
}

// round 8
// speedup vs baseline: 1.1422x; 1.1422x over previous
#include <cuda_runtime.h>
#include <cuda_fp16.h>
#include <cstddef>
#include <cstdint>

// ---------------------------------------------------------------------------
// GeoDynamicLayer: out = x @ W^T, W = RK4(dU/dt = U A + G).
// Factored RK4 (24-dim row space) + single-pass fp16 HMMA GEMM
// (x, W rounded to fp16; fp32 accumulate; rel_err ~3e-4 < 1e-3).
// ---------------------------------------------------------------------------

__device__ float g_partial[512 * 512];
__device__ float g_ab[16];
__device__ float g_S[24 * 16];
__device__ float g_F0[1024 * 24];
__device__ float g_P[1024 * 24];
__device__ __half g_x16[32768 * 512];
__device__ __half g_W16[1024 * 512];

// ---------------- Stage 1: convert x -> fp16 + column partial sums ----------
// 512 blocks x 256 threads; block handles 64 rows. float4 loads, 8B stores.
__global__ void convert_reduce_k(const float* __restrict__ x) {
    __shared__ float4 sm[256];
    int t = threadIdx.x;
    int cg = t & 127;                    // float4 column group (col = 4*cg)
    int rh = t >> 7;                     // row half 0/1
    int row0 = blockIdx.x * 64 + rh * 32;
    float4 s = make_float4(0.f, 0.f, 0.f, 0.f);
    #pragma unroll 4
    for (int i = 0; i < 32; ++i) {
        size_t idx = (size_t)(row0 + i) * 512 + cg * 4;
        float4 v = *(const float4*)(x + idx);
        s.x += v.x; s.y += v.y; s.z += v.z; s.w += v.w;
        union { __half2 h[2]; uint2 u; } cv;
        cv.h[0] = __floats2half2_rn(v.x, v.y);
        cv.h[1] = __floats2half2_rn(v.z, v.w);
        *(uint2*)(g_x16 + idx) = cv.u;
    }
    sm[t] = s;
    __syncthreads();
    if (t < 128) {
        float4 a = sm[t], b = sm[t + 128];
        a.x += b.x; a.y += b.y; a.z += b.z; a.w += b.w;
        *(float4*)(g_partial + blockIdx.x * 512 + cg * 4) = a;
    }
}

// ---------------- Stage 2: xbar, abar, bbar ---------------------------------
__global__ void finalize_ab_k(const float* __restrict__ Wa,
                              const float* __restrict__ Wb) {
    __shared__ float sx[512];
    int t = threadIdx.x;
    float s = 0.f;
    #pragma unroll 8
    for (int p = 0; p < 512; ++p) s += g_partial[p * 512 + t];
    s *= (1.0f / 32768.0f);
    sx[t] = s;
    __syncthreads();
    int w = t >> 5, lane = t & 31;
    const float* Wm = (w < 8) ? Wa : Wb;
    int r = w & 7;
    float acc = 0.f;
    #pragma unroll
    for (int q = 0; q < 16; ++q) {
        int i = lane + q * 32;
        acc += sx[i] * Wm[i * 8 + r];
    }
    #pragma unroll
    for (int off = 16; off; off >>= 1)
        acc += __shfl_xor_sync(0xffffffffu, acc, off);
    if (lane == 0) g_ab[w] = acc;
}

// ---------------- Stage 3: S (24x16) ----------------------------------------
__global__ void compute_S_k(const float* __restrict__ La,
                            const float* __restrict__ Ra,
                            const float* __restrict__ Rb) {
    int gw = (blockIdx.x * blockDim.x + threadIdx.x) >> 5;
    int lane = threadIdx.x & 31;
    if (gw >= 384) return;
    int k = gw >> 4, c = gw & 15;
    const float* Vk = (k < 8) ? La : ((k < 16) ? Ra : Rb);
    int kk = k & 7;
    const float* M = (c < 8) ? Ra : La;
    int r = c & 7;
    float acc = 0.f;
    #pragma unroll
    for (int q = 0; q < 16; ++q) {
        int i = lane + q * 32;
        acc += Vk[i * 8 + kk] * M[i * 8 + r];
    }
    #pragma unroll
    for (int off = 16; off; off >>= 1)
        acc += __shfl_xor_sync(0xffffffffu, acc, off);
    if (lane == 0) {
        float d = g_ab[r];
        g_S[k * 16 + c] = (c < 8) ? (-acc * d) : (acc * d);
    }
}

// ---------------- Stage 4: F0 (1024x24) -------------------------------------
__global__ void compute_F0_k(const float* __restrict__ U0,
                             const float* __restrict__ La,
                             const float* __restrict__ Ra,
                             const float* __restrict__ Lb) {
    int w = (blockIdx.x * blockDim.x + threadIdx.x) >> 5;
    int lane = threadIdx.x & 31;
    const float* u = U0 + (size_t)w * 512;
    float accA[8] = {0, 0, 0, 0, 0, 0, 0, 0};
    float accR[8] = {0, 0, 0, 0, 0, 0, 0, 0};
    #pragma unroll
    for (int q = 0; q < 16; ++q) {
        int i = lane + q * 32;
        float uv = u[i];
        float4 la0 = *(const float4*)(La + i * 8);
        float4 la1 = *(const float4*)(La + i * 8 + 4);
        float4 ra0 = *(const float4*)(Ra + i * 8);
        float4 ra1 = *(const float4*)(Ra + i * 8 + 4);
        accA[0] += uv * la0.x; accA[1] += uv * la0.y;
        accA[2] += uv * la0.z; accA[3] += uv * la0.w;
        accA[4] += uv * la1.x; accA[5] += uv * la1.y;
        accA[6] += uv * la1.z; accA[7] += uv * la1.w;
        accR[0] += uv * ra0.x; accR[1] += uv * ra0.y;
        accR[2] += uv * ra0.z; accR[3] += uv * ra0.w;
        accR[4] += uv * ra1.x; accR[5] += uv * ra1.y;
        accR[6] += uv * ra1.z; accR[7] += uv * ra1.w;
    }
    #pragma unroll
    for (int off = 16; off; off >>= 1) {
        #pragma unroll
        for (int r = 0; r < 8; ++r) {
            accA[r] += __shfl_xor_sync(0xffffffffu, accA[r], off);
            accR[r] += __shfl_xor_sync(0xffffffffu, accR[r], off);
        }
    }
    if (lane == 0) {
        #pragma unroll
        for (int r = 0; r < 8; ++r) {
            float da = g_ab[r];
            g_F0[w * 24 + r]     = -da * accR[r];
            g_F0[w * 24 + 8 + r] =  da * accA[r];
            float gb = 0.f;
            if (w >= 512) gb = g_ab[8 + r] * Lb[(w - 512) * 8 + r];
            g_F0[w * 24 + 16 + r] = gb;
        }
    }
}

// ---------------- Stage 5: RK4 in 24-dim coefficient space ------------------
__global__ void rk4_k() {
    int row = (blockIdx.x * blockDim.x + threadIdx.x) >> 5;
    int lane = threadIdx.x & 31;
    float scol[24];
    #pragma unroll
    for (int k = 0; k < 24; ++k)
        scol[k] = (lane < 16) ? g_S[k * 16 + lane] : 0.f;
    float f0 = (lane < 24) ? g_F0[row * 24 + lane] : 0.f;
    float p[24];
    #pragma unroll
    for (int k = 0; k < 24; ++k) p[k] = 0.f;
    const float dt = 1.0f / 8.0f;
    for (int step = 0; step < 8; ++step) {
        float v[24], acc[24];
        #pragma unroll
        for (int k = 0; k < 24; ++k) v[k] = p[k];
        float kc = f0;
        #pragma unroll
        for (int k = 0; k < 24; ++k) kc += v[k] * scol[k];
        #pragma unroll
        for (int k = 0; k < 24; ++k) {
            float kf = __shfl_sync(0xffffffffu, kc, k);
            acc[k] = kf;
            v[k] = p[k] + 0.5f * dt * kf;
        }
        kc = f0;
        #pragma unroll
        for (int k = 0; k < 24; ++k) kc += v[k] * scol[k];
        #pragma unroll
        for (int k = 0; k < 24; ++k) {
            float kf = __shfl_sync(0xffffffffu, kc, k);
            acc[k] += 2.0f * kf;
            v[k] = p[k] + 0.5f * dt * kf;
        }
        kc = f0;
        #pragma unroll
        for (int k = 0; k < 24; ++k) kc += v[k] * scol[k];
        #pragma unroll
        for (int k = 0; k < 24; ++k) {
            float kf = __shfl_sync(0xffffffffu, kc, k);
            acc[k] += 2.0f * kf;
            v[k] = p[k] + dt * kf;
        }
        kc = f0;
        #pragma unroll
        for (int k = 0; k < 24; ++k) kc += v[k] * scol[k];
        #pragma unroll
        for (int k = 0; k < 24; ++k) {
            float kf = __shfl_sync(0xffffffffu, kc, k);
            acc[k] += kf;
        }
        #pragma unroll
        for (int k = 0; k < 24; ++k) p[k] += (dt / 6.0f) * acc[k];
    }
    if (lane < 24) g_P[row * 24 + lane] = p[lane];
}

// ---------------- Stage 6: W = U0 + P V2^T  -> fp16 -------------------------
__global__ void expand_W_k(const float* __restrict__ U0,
                           const float* __restrict__ La,
                           const float* __restrict__ Ra,
                           const float* __restrict__ Rb) {
    __shared__ float sP[8 * 24];
    int t = threadIdx.x;
    int o0 = blockIdx.x * 8;
    if (t < 192) sP[t] = g_P[o0 * 24 + t];
    __syncthreads();
    #pragma unroll
    for (int half = 0; half < 2; ++half) {
        int i = t + half * 256;
        float v2[24];
        float4 q;
        q = *(const float4*)(La + i * 8);
        v2[0] = q.x; v2[1] = q.y; v2[2] = q.z; v2[3] = q.w;
        q = *(const float4*)(La + i * 8 + 4);
        v2[4] = q.x; v2[5] = q.y; v2[6] = q.z; v2[7] = q.w;
        q = *(const float4*)(Ra + i * 8);
        v2[8] = q.x; v2[9] = q.y; v2[10] = q.z; v2[11] = q.w;
        q = *(const float4*)(Ra + i * 8 + 4);
        v2[12] = q.x; v2[13] = q.y; v2[14] = q.z; v2[15] = q.w;
        q = *(const float4*)(Rb + i * 8);
        v2[16] = q.x; v2[17] = q.y; v2[18] = q.z; v2[19] = q.w;
        q = *(const float4*)(Rb + i * 8 + 4);
        v2[20] = q.x; v2[21] = q.y; v2[22] = q.z; v2[23] = q.w;
        #pragma unroll
        for (int r = 0; r < 8; ++r) {
            float accv = U0[(size_t)(o0 + r) * 512 + i];
            #pragma unroll
            for (int k = 0; k < 24; ++k) accv += sP[r * 24 + k] * v2[k];
            g_W16[(size_t)(o0 + r) * 512 + i] = __float2half_rn(accv);
        }
    }
}

// ---------------- Stage 7: fp16 HMMA GEMM  out = x @ W^T --------------------
#define CP16(sa, ga) \
    asm volatile("cp.async.cg.shared.global [%0], [%1], 16;\n" :: "r"(sa), "l"(ga))

__device__ __forceinline__ void ldm_x4(uint32_t& r0, uint32_t& r1,
                                       uint32_t& r2, uint32_t& r3, uint32_t a) {
    asm volatile("ldmatrix.sync.aligned.m8n8.x4.shared.b16 {%0,%1,%2,%3}, [%4];"
                 : "=r"(r0), "=r"(r1), "=r"(r2), "=r"(r3) : "r"(a));
}

__device__ __forceinline__ void mma16816(float* c, const uint32_t* a,
                                         const uint32_t* b) {
    asm volatile(
        "mma.sync.aligned.m16n8k16.row.col.f32.f16.f16.f32 "
        "{%0,%1,%2,%3}, {%4,%5,%6,%7}, {%8,%9}, {%0,%1,%2,%3};"
        : "+f"(c[0]), "+f"(c[1]), "+f"(c[2]), "+f"(c[3])
        : "r"(a[0]), "r"(a[1]), "r"(a[2]), "r"(a[3]), "r"(b[0]), "r"(b[1]));
}

__global__ __launch_bounds__(256) void gemm_tc_k(float* __restrict__ out) {
    __shared__ __align__(16) __half smA[2][128 * 5 * 8];
    __shared__ __align__(16) __half smB[2][128 * 5 * 8];

    int tid = threadIdx.x;
    int lane = tid & 31;
    int w = tid >> 5;
    int wm = (w & 3) * 32;
    int wn = (w >> 2) * 64;
    int bm = blockIdx.y * 128;
    int bn = blockIdx.x * 128;

    uint32_t saA[2], saB[2];
    saA[0] = (uint32_t)__cvta_generic_to_shared(&smA[0][0]);
    saA[1] = (uint32_t)__cvta_generic_to_shared(&smA[1][0]);
    saB[0] = (uint32_t)__cvta_generic_to_shared(&smB[0][0]);
    saB[1] = (uint32_t)__cvta_generic_to_shared(&smB[1][0]);

    float c[2][8][4];
    #pragma unroll
    for (int mi = 0; mi < 2; ++mi)
        #pragma unroll
        for (int ni = 0; ni < 8; ++ni)
            #pragma unroll
            for (int q = 0; q < 4; ++q) c[mi][ni][q] = 0.f;

    int lr0 = tid >> 2;
    int lu = tid & 3;

    auto issue_chunk = [&](int i, int buf) {
        int ko = i << 5;
        #pragma unroll
        for (int j = 0; j < 2; ++j) {
            int r = lr0 + j * 64;
            const __half* ga = g_x16 + (size_t)(bm + r) * 512 + ko + lu * 8;
            CP16(saA[buf] + ((r * 5 + lu) << 4), ga);
            const __half* gb = g_W16 + (size_t)(bn + r) * 512 + ko + lu * 8;
            CP16(saB[buf] + ((r * 5 + lu) << 4), gb);
        }
        asm volatile("cp.async.commit_group;\n" ::);
    };

    issue_chunk(0, 0);

    int mg = lane >> 3, rr = lane & 7;

    for (int i = 0; i < 16; ++i) {
        int buf = i & 1;
        if (i + 1 < 16) {
            issue_chunk(i + 1, buf ^ 1);
            asm volatile("cp.async.wait_group 1;\n" ::);
        } else {
            asm volatile("cp.async.wait_group 0;\n" ::);
        }
        __syncthreads();

        #pragma unroll
        for (int ks = 0; ks < 2; ++ks) {
            uint32_t a[2][4];
            #pragma unroll
            for (int mi = 0; mi < 2; ++mi) {
                int row = wm + mi * 16 + (mg & 1) * 8 + rr;
                int ku = ks * 2 + (mg >> 1);
                ldm_x4(a[mi][0], a[mi][1], a[mi][2], a[mi][3],
                       saA[buf] + ((row * 5 + ku) << 4));
            }
            uint32_t b[8][2];
            #pragma unroll
            for (int j = 0; j < 4; ++j) {
                int row = wn + j * 16 + (mg >> 1) * 8 + rr;
                int ku = ks * 2 + (mg & 1);
                ldm_x4(b[2 * j][0], b[2 * j][1], b[2 * j + 1][0], b[2 * j + 1][1],
                       saB[buf] + ((row * 5 + ku) << 4));
            }
            #pragma unroll
            for (int mi = 0; mi < 2; ++mi)
                #pragma unroll
                for (int ni = 0; ni < 8; ++ni)
                    mma16816(c[mi][ni], a[mi], b[ni]);
        }
        __syncthreads();
    }

    int gid = lane >> 2, tig = lane & 3;
    #pragma unroll
    for (int mi = 0; mi < 2; ++mi) {
        #pragma unroll
        for (int ni = 0; ni < 8; ++ni) {
            int row0 = bm + wm + mi * 16 + gid;
            int col = bn + wn + ni * 8 + tig * 2;
            float2* p0 = (float2*)(out + (size_t)row0 * 1024 + col);
            *p0 = make_float2(c[mi][ni][0], c[mi][ni][1]);
            float2* p1 = (float2*)(out + (size_t)(row0 + 8) * 1024 + col);
            *p1 = make_float2(c[mi][ni][2], c[mi][ni][3]);
        }
    }
}

// ---------------------------------------------------------------------------
extern "C" void kernel_launch(void* const* d_in, const int* in_sizes, int n_in,
                              void* d_out, int out_size) {
    const float* x  = (const float*)d_in[0];
    const float* U0 = (const float*)d_in[1];
    const float* Wa = (const float*)d_in[2];
    const float* La = (const float*)d_in[3];
    const float* Ra = (const float*)d_in[4];
    const float* Wb = (const float*)d_in[5];
    const float* Lb = (const float*)d_in[6];
    const float* Rb = (const float*)d_in[7];
    float* out = (float*)d_out;
    (void)in_sizes; (void)n_in; (void)out_size;

    convert_reduce_k<<<512, 256>>>(x);
    finalize_ab_k<<<1, 512>>>(Wa, Wb);
    compute_S_k<<<48, 256>>>(La, Ra, Rb);
    compute_F0_k<<<128, 256>>>(U0, La, Ra, Lb);
    rk4_k<<<128, 256>>>();
    expand_W_k<<<128, 256>>>(U0, La, Ra, Rb);
    gemm_tc_k<<<dim3(8, 256), 256>>>(out);
}

// round 9
// speedup vs baseline: 1.2812x; 1.1218x over previous
#include <cuda_runtime.h>
#include <cuda_fp16.h>
#include <cstddef>
#include <cstdint>

// ---------------------------------------------------------------------------
// GeoDynamicLayer: out = x @ W^T, W = RK4(dU/dt = U A + G).
// Factored RK4 (24-dim row space) + single-pass fp16 HMMA GEMM
// (x, W rounded to fp16; fp32 accumulate; rel_err ~3e-4 < 1e-3).
// ---------------------------------------------------------------------------

__device__ float g_partial[256 * 512];
__device__ float g_ab[16];
__device__ float g_S[24 * 16];
__device__ float g_P[1024 * 24];
__device__ __half g_x16[32768 * 512];
__device__ __half g_W16[1024 * 512];

// ---------------- Stage 1: convert x -> fp16 + column partial sums ----------
__global__ void convert_reduce_k(const float* __restrict__ x) {
    int t = threadIdx.x;                 // 0..511 = column
    int rowStart = blockIdx.x * 128;
    const float* p = x + (size_t)rowStart * 512 + t;
    float s = 0.f;
    #pragma unroll 4
    for (int r = 0; r < 128; ++r) {
        float v = p[(size_t)r * 512];
        s += v;
        g_x16[(size_t)(rowStart + r) * 512 + t] = __float2half_rn(v);
    }
    g_partial[blockIdx.x * 512 + t] = s;
}

// ---------------- Stage 2: xbar, abar, bbar ---------------------------------
__global__ void finalize_ab_k(const float* __restrict__ Wa,
                              const float* __restrict__ Wb) {
    __shared__ float sx[512];
    int t = threadIdx.x;
    float s = 0.f;
    #pragma unroll 8
    for (int p = 0; p < 256; ++p) s += g_partial[p * 512 + t];
    s *= (1.0f / 32768.0f);
    sx[t] = s;
    __syncthreads();
    int w = t >> 5, lane = t & 31;
    const float* Wm = (w < 8) ? Wa : Wb;
    int r = w & 7;
    float acc = 0.f;
    #pragma unroll
    for (int q = 0; q < 16; ++q) {
        int i = lane + q * 32;
        acc += sx[i] * Wm[i * 8 + r];
    }
    #pragma unroll
    for (int off = 16; off; off >>= 1)
        acc += __shfl_xor_sync(0xffffffffu, acc, off);
    if (lane == 0) g_ab[w] = acc;
}

// ---------------- Stage 3: S (24x16) ----------------------------------------
__global__ void compute_S_k(const float* __restrict__ La,
                            const float* __restrict__ Ra,
                            const float* __restrict__ Rb) {
    int gw = (blockIdx.x * blockDim.x + threadIdx.x) >> 5;
    int lane = threadIdx.x & 31;
    if (gw >= 384) return;
    int k = gw >> 4, c = gw & 15;
    const float* Vk = (k < 8) ? La : ((k < 16) ? Ra : Rb);
    int kk = k & 7;
    const float* M = (c < 8) ? Ra : La;
    int r = c & 7;
    float acc = 0.f;
    #pragma unroll
    for (int q = 0; q < 16; ++q) {
        int i = lane + q * 32;
        acc += Vk[i * 8 + kk] * M[i * 8 + r];
    }
    #pragma unroll
    for (int off = 16; off; off >>= 1)
        acc += __shfl_xor_sync(0xffffffffu, acc, off);
    if (lane == 0) {
        float d = g_ab[r];
        g_S[k * 16 + c] = (c < 8) ? (-acc * d) : (acc * d);
    }
}

// ---------------- Stage 4+5 fused: F0 row + RK4 in coefficient space --------
// Warp = one row of U. xor-reduction leaves accA/accR valid in ALL lanes, so
// each lane builds its own f0 component and RK4 runs immediately (no global
// F0 round-trip, one launch fewer).
__global__ void f0_rk4_k(const float* __restrict__ U0,
                         const float* __restrict__ La,
                         const float* __restrict__ Ra,
                         const float* __restrict__ Lb) {
    int w = (blockIdx.x * blockDim.x + threadIdx.x) >> 5;   // row 0..1023
    int lane = threadIdx.x & 31;
    const float* u = U0 + (size_t)w * 512;
    float accA[8] = {0, 0, 0, 0, 0, 0, 0, 0};
    float accR[8] = {0, 0, 0, 0, 0, 0, 0, 0};
    #pragma unroll
    for (int q = 0; q < 16; ++q) {
        int i = lane + q * 32;
        float uv = u[i];
        float4 la0 = *(const float4*)(La + i * 8);
        float4 la1 = *(const float4*)(La + i * 8 + 4);
        float4 ra0 = *(const float4*)(Ra + i * 8);
        float4 ra1 = *(const float4*)(Ra + i * 8 + 4);
        accA[0] += uv * la0.x; accA[1] += uv * la0.y;
        accA[2] += uv * la0.z; accA[3] += uv * la0.w;
        accA[4] += uv * la1.x; accA[5] += uv * la1.y;
        accA[6] += uv * la1.z; accA[7] += uv * la1.w;
        accR[0] += uv * ra0.x; accR[1] += uv * ra0.y;
        accR[2] += uv * ra0.z; accR[3] += uv * ra0.w;
        accR[4] += uv * ra1.x; accR[5] += uv * ra1.y;
        accR[6] += uv * ra1.z; accR[7] += uv * ra1.w;
    }
    #pragma unroll
    for (int off = 16; off; off >>= 1) {
        #pragma unroll
        for (int r = 0; r < 8; ++r) {
            accA[r] += __shfl_xor_sync(0xffffffffu, accA[r], off);
            accR[r] += __shfl_xor_sync(0xffffffffu, accR[r], off);
        }
    }
    // lane c holds f0_c:  c<8: -ab[c]*accR[c];  8..15: ab[c-8]*accA[c-8];
    // 16..23: forcing row (only for w>=512).
    float f0 = 0.f;
    #pragma unroll
    for (int r = 0; r < 8; ++r) {
        float da = g_ab[r];
        if (lane == r)     f0 = -da * accR[r];
        if (lane == r + 8) f0 =  da * accA[r];
    }
    if (lane >= 16 && lane < 24 && w >= 512)
        f0 = g_ab[8 + (lane - 16)] * Lb[(w - 512) * 8 + (lane - 16)];

    float scol[24];
    #pragma unroll
    for (int k = 0; k < 24; ++k)
        scol[k] = (lane < 16) ? g_S[k * 16 + lane] : 0.f;
    float p[24];
    #pragma unroll
    for (int k = 0; k < 24; ++k) p[k] = 0.f;
    const float dt = 1.0f / 8.0f;
    for (int step = 0; step < 8; ++step) {
        float v[24], acc[24];
        #pragma unroll
        for (int k = 0; k < 24; ++k) v[k] = p[k];
        float kc = f0;
        #pragma unroll
        for (int k = 0; k < 24; ++k) kc += v[k] * scol[k];
        #pragma unroll
        for (int k = 0; k < 24; ++k) {
            float kf = __shfl_sync(0xffffffffu, kc, k);
            acc[k] = kf;
            v[k] = p[k] + 0.5f * dt * kf;
        }
        kc = f0;
        #pragma unroll
        for (int k = 0; k < 24; ++k) kc += v[k] * scol[k];
        #pragma unroll
        for (int k = 0; k < 24; ++k) {
            float kf = __shfl_sync(0xffffffffu, kc, k);
            acc[k] += 2.0f * kf;
            v[k] = p[k] + 0.5f * dt * kf;
        }
        kc = f0;
        #pragma unroll
        for (int k = 0; k < 24; ++k) kc += v[k] * scol[k];
        #pragma unroll
        for (int k = 0; k < 24; ++k) {
            float kf = __shfl_sync(0xffffffffu, kc, k);
            acc[k] += 2.0f * kf;
            v[k] = p[k] + dt * kf;
        }
        kc = f0;
        #pragma unroll
        for (int k = 0; k < 24; ++k) kc += v[k] * scol[k];
        #pragma unroll
        for (int k = 0; k < 24; ++k) {
            float kf = __shfl_sync(0xffffffffu, kc, k);
            acc[k] += kf;
        }
        #pragma unroll
        for (int k = 0; k < 24; ++k) p[k] += (dt / 6.0f) * acc[k];
    }
    if (lane < 24) g_P[w * 24 + lane] = p[lane];
}

// ---------------- Stage 6: W = U0 + P V2^T  -> fp16 -------------------------
__global__ void expand_W_k(const float* __restrict__ U0,
                           const float* __restrict__ La,
                           const float* __restrict__ Ra,
                           const float* __restrict__ Rb) {
    __shared__ float sP[8 * 24];
    int t = threadIdx.x;
    int o0 = blockIdx.x * 8;
    if (t < 192) sP[t] = g_P[o0 * 24 + t];
    __syncthreads();
    #pragma unroll
    for (int half = 0; half < 2; ++half) {
        int i = t + half * 256;
        float v2[24];
        float4 q;
        q = *(const float4*)(La + i * 8);
        v2[0] = q.x; v2[1] = q.y; v2[2] = q.z; v2[3] = q.w;
        q = *(const float4*)(La + i * 8 + 4);
        v2[4] = q.x; v2[5] = q.y; v2[6] = q.z; v2[7] = q.w;
        q = *(const float4*)(Ra + i * 8);
        v2[8] = q.x; v2[9] = q.y; v2[10] = q.z; v2[11] = q.w;
        q = *(const float4*)(Ra + i * 8 + 4);
        v2[12] = q.x; v2[13] = q.y; v2[14] = q.z; v2[15] = q.w;
        q = *(const float4*)(Rb + i * 8);
        v2[16] = q.x; v2[17] = q.y; v2[18] = q.z; v2[19] = q.w;
        q = *(const float4*)(Rb + i * 8 + 4);
        v2[20] = q.x; v2[21] = q.y; v2[22] = q.z; v2[23] = q.w;
        #pragma unroll
        for (int r = 0; r < 8; ++r) {
            float accv = U0[(size_t)(o0 + r) * 512 + i];
            #pragma unroll
            for (int k = 0; k < 24; ++k) accv += sP[r * 24 + k] * v2[k];
            g_W16[(size_t)(o0 + r) * 512 + i] = __float2half_rn(accv);
        }
    }
}

// ---------------- Stage 7: fp16 HMMA GEMM  out = x @ W^T --------------------
// 3-stage cp.async pipeline (60KB dynamic smem), ONE __syncthreads per chunk.
#define CP16(sa, ga) \
    asm volatile("cp.async.cg.shared.global [%0], [%1], 16;\n" :: "r"(sa), "l"(ga))

__device__ __forceinline__ void ldm_x4(uint32_t& r0, uint32_t& r1,
                                       uint32_t& r2, uint32_t& r3, uint32_t a) {
    asm volatile("ldmatrix.sync.aligned.m8n8.x4.shared.b16 {%0,%1,%2,%3}, [%4];"
                 : "=r"(r0), "=r"(r1), "=r"(r2), "=r"(r3) : "r"(a));
}

__device__ __forceinline__ void mma16816(float* c, const uint32_t* a,
                                         const uint32_t* b) {
    asm volatile(
        "mma.sync.aligned.m16n8k16.row.col.f32.f16.f16.f32 "
        "{%0,%1,%2,%3}, {%4,%5,%6,%7}, {%8,%9}, {%0,%1,%2,%3};"
        : "+f"(c[0]), "+f"(c[1]), "+f"(c[2]), "+f"(c[3])
        : "r"(a[0]), "r"(a[1]), "r"(a[2]), "r"(a[3]), "r"(b[0]), "r"(b[1]));
}

__global__ __launch_bounds__(256) void gemm_tc_k(float* __restrict__ out) {
    extern __shared__ __align__(16) char dynsm[];
    // stage s: A at s*20480, B at s*20480 + 10240 (bytes); 3 stages = 60KB
    uint32_t base = (uint32_t)__cvta_generic_to_shared(dynsm);

    int tid = threadIdx.x;
    int lane = tid & 31;
    int w = tid >> 5;
    int wm = (w & 3) * 32;
    int wn = (w >> 2) * 64;
    int bm = blockIdx.y * 128;
    int bn = blockIdx.x * 128;

    float c[2][8][4];
    #pragma unroll
    for (int mi = 0; mi < 2; ++mi)
        #pragma unroll
        for (int ni = 0; ni < 8; ++ni)
            #pragma unroll
            for (int q = 0; q < 4; ++q) c[mi][ni][q] = 0.f;

    int lr0 = tid >> 2;
    int lu = tid & 3;

    auto issue_chunk = [&](int i) {
        int st = i % 3;
        uint32_t sA = base + st * 20480;
        uint32_t sB = sA + 10240;
        int ko = i << 5;
        #pragma unroll
        for (int j = 0; j < 2; ++j) {
            int r = lr0 + j * 64;
            const __half* ga = g_x16 + (size_t)(bm + r) * 512 + ko + lu * 8;
            CP16(sA + ((r * 5 + lu) << 4), ga);
            const __half* gb = g_W16 + (size_t)(bn + r) * 512 + ko + lu * 8;
            CP16(sB + ((r * 5 + lu) << 4), gb);
        }
        asm volatile("cp.async.commit_group;\n" ::);
    };

    issue_chunk(0);
    issue_chunk(1);

    int mg = lane >> 3, rr = lane & 7;

    for (int i = 0; i < 16; ++i) {
        if (i < 15) asm volatile("cp.async.wait_group 1;\n" ::);
        else        asm volatile("cp.async.wait_group 0;\n" ::);
        __syncthreads();
        if (i + 2 < 16) issue_chunk(i + 2);

        int st = i % 3;
        uint32_t sA = base + st * 20480;
        uint32_t sB = sA + 10240;
        #pragma unroll
        for (int ks = 0; ks < 2; ++ks) {
            uint32_t a[2][4];
            #pragma unroll
            for (int mi = 0; mi < 2; ++mi) {
                int row = wm + mi * 16 + (mg & 1) * 8 + rr;
                int ku = ks * 2 + (mg >> 1);
                ldm_x4(a[mi][0], a[mi][1], a[mi][2], a[mi][3],
                       sA + ((row * 5 + ku) << 4));
            }
            uint32_t b[8][2];
            #pragma unroll
            for (int j = 0; j < 4; ++j) {
                int row = wn + j * 16 + (mg >> 1) * 8 + rr;
                int ku = ks * 2 + (mg & 1);
                ldm_x4(b[2 * j][0], b[2 * j][1], b[2 * j + 1][0], b[2 * j + 1][1],
                       sB + ((row * 5 + ku) << 4));
            }
            #pragma unroll
            for (int mi = 0; mi < 2; ++mi)
                #pragma unroll
                for (int ni = 0; ni < 8; ++ni)
                    mma16816(c[mi][ni], a[mi], b[ni]);
        }
    }

    int gid = lane >> 2, tig = lane & 3;
    #pragma unroll
    for (int mi = 0; mi < 2; ++mi) {
        #pragma unroll
        for (int ni = 0; ni < 8; ++ni) {
            int row0 = bm + wm + mi * 16 + gid;
            int col = bn + wn + ni * 8 + tig * 2;
            float2* p0 = (float2*)(out + (size_t)row0 * 1024 + col);
            *p0 = make_float2(c[mi][ni][0], c[mi][ni][1]);
            float2* p1 = (float2*)(out + (size_t)(row0 + 8) * 1024 + col);
            *p1 = make_float2(c[mi][ni][2], c[mi][ni][3]);
        }
    }
}

// ---------------------------------------------------------------------------
extern "C" void kernel_launch(void* const* d_in, const int* in_sizes, int n_in,
                              void* d_out, int out_size) {
    const float* x  = (const float*)d_in[0];
    const float* U0 = (const float*)d_in[1];
    const float* Wa = (const float*)d_in[2];
    const float* La = (const float*)d_in[3];
    const float* Ra = (const float*)d_in[4];
    const float* Wb = (const float*)d_in[5];
    const float* Lb = (const float*)d_in[6];
    const float* Rb = (const float*)d_in[7];
    float* out = (float*)d_out;
    (void)in_sizes; (void)n_in; (void)out_size;

    static int smem_set = 0;
    const int dyn_smem = 3 * 20480;      // 60 KB
    if (!smem_set) {
        cudaFuncSetAttribute(gemm_tc_k,
                             cudaFuncAttributeMaxDynamicSharedMemorySize,
                             dyn_smem);
        smem_set = 1;
    }

    convert_reduce_k<<<256, 512>>>(x);
    finalize_ab_k<<<1, 512>>>(Wa, Wb);
    compute_S_k<<<48, 256>>>(La, Ra, Rb);
    f0_rk4_k<<<128, 256>>>(U0, La, Ra, Lb);
    expand_W_k<<<128, 256>>>(U0, La, Ra, Rb);
    gemm_tc_k<<<dim3(8, 256), 256, dyn_smem>>>(out);
}